// round 15
// baseline (speedup 1.0000x reference)
#include <cuda_runtime.h>
#include <cuda_bf16.h>

#define BB 128
#define NN 4096
#define SS 8
#define DD 64
#define NTOK (BB*NN)
#define NPART 16
#define TOKPB (NN/NPART)
#define CHUNK 64
#define NCHUNK (TOKPB/CHUNK)
#define NROW (BB*SS)

__device__ float g_x[NTOK*DD];
__device__ float g_prep[NPART*NROW*DD];
__device__ float g_denp[NPART*NROW];
__device__ float g_qk[NROW*DD];
__device__ float g_slots[NROW*DD];

__device__ float g_vwT[64*64];
__device__ float g_wihT[64*192];
__device__ float g_whhT[64*192];
__device__ float g_w1T[64*128];
__device__ float g_w2T[128*64];
__device__ float g_qwT[64*64];

// side stream + events, created at static-init (before harness mem baseline)
struct HxStreams {
    cudaStream_t s1;
    cudaEvent_t e_tr, e_init, e_attn, e_wn;
    HxStreams(){
        cudaStreamCreateWithFlags(&s1, cudaStreamNonBlocking);
        cudaEventCreateWithFlags(&e_tr,   cudaEventDisableTiming);
        cudaEventCreateWithFlags(&e_init, cudaEventDisableTiming);
        cudaEventCreateWithFlags(&e_attn, cudaEventDisableTiming);
        cudaEventCreateWithFlags(&e_wn,   cudaEventDisableTiming);
    }
};
static HxStreams g_hx;

typedef unsigned long long u64;
__device__ __forceinline__ u64 pk2(float x, float y){
    u64 r; asm("mov.b64 %0,{%1,%2};" : "=l"(r) : "f"(x), "f"(y)); return r;
}
__device__ __forceinline__ void up2(u64 v, float &x, float &y){
    asm("mov.b64 {%0,%1},%2;" : "=f"(x), "=f"(y) : "l"(v));
}
__device__ __forceinline__ u64 ffma2(u64 a, u64 b, u64 c){
    u64 d; asm("fma.rn.f32x2 %0,%1,%2,%3;" : "=l"(d) : "l"(a), "l"(b), "l"(c)); return d;
}

// ---------------- weight transpose (once per call) ----------------
__global__ void k_tr(const float* __restrict__ vw, const float* __restrict__ wih,
                     const float* __restrict__ whh, const float* __restrict__ w1,
                     const float* __restrict__ w2,  const float* __restrict__ qw){
    int i = blockIdx.x*256 + threadIdx.x;
    if (i < 4096){
        g_vwT[(i&63)*64 + (i>>6)] = vw[i];
    } else if (i < 16384){
        int j = i - 4096;  g_wihT[(j&63)*192 + (j>>6)] = wih[j];
    } else if (i < 28672){
        int j = i - 16384; g_whhT[(j&63)*192 + (j>>6)] = whh[j];
    } else if (i < 36864){
        int j = i - 28672; g_w1T[(j&63)*128 + (j>>6)] = w1[j];
    } else if (i < 45056){
        int j = i - 36864; g_w2T[(j&127)*64 + (j>>7)] = w2[j];
    } else if (i < 49152){
        int j = i - 45056; g_qwT[(j&63)*64 + (j>>6)] = qw[j];
    }
}

// ---------------- x = LayerNorm(inputs), 4-token ILP batching --------------
__global__ void k_prep(const float* __restrict__ inp,
                       const float* __restrict__ nw,
                       const float* __restrict__ nb){
    int gw = (blockIdx.x*blockDim.x + threadIdx.x) >> 5;
    int lane = threadIdx.x & 31;
    int nwarp = (gridDim.x*blockDim.x) >> 5;
    float2 wv = ((const float2*)nw)[lane];
    float2 bv = ((const float2*)nb)[lane];
    for (int t0 = gw*4; t0 < NTOK; t0 += nwarp*4){
        float2 v[4];
        #pragma unroll
        for (int j = 0; j < 4; j++)
            v[j] = ((const float2*)inp)[(size_t)(t0+j)*32 + lane];
        float s[4], q[4];
        #pragma unroll
        for (int j = 0; j < 4; j++){
            s[j] = v[j].x + v[j].y;
            q[j] = v[j].x*v[j].x + v[j].y*v[j].y;
        }
        #pragma unroll
        for (int o = 16; o; o >>= 1){
            #pragma unroll
            for (int j = 0; j < 4; j++){
                s[j] += __shfl_xor_sync(~0u, s[j], o);
                q[j] += __shfl_xor_sync(~0u, q[j], o);
            }
        }
        #pragma unroll
        for (int j = 0; j < 4; j++){
            float m = s[j]*(1.f/64.f);
            float rs = rsqrtf(q[j]*(1.f/64.f) - m*m + 1e-5f);
            float2 o2;
            o2.x = (v[j].x-m)*rs*wv.x + bv.x;
            o2.y = (v[j].y-m)*rs*wv.y + bv.y;
            ((float2*)g_x)[(size_t)(t0+j)*32 + lane] = o2;
        }
    }
}

// ---------------- attention accumulation, grid (16 parts, 128 batch) -------
__global__ void __launch_bounds__(256, 3) k_attn(int fin, float* __restrict__ out_w){
    int p = blockIdx.x, b = blockIdx.y;
    int tid = threadIdx.x, lane = tid & 31, w = tid >> 5;
    __shared__ float xs[CHUNK][68];
    __shared__ u64  ws2[CHUNK][10];
    __shared__ float lgs[CHUNK][12];
    __shared__ u64  qq[16][16];

    {
        int i = tid >> 4, j = tid & 15;
        int s = 4*(j>>3) + ((j>>1)&3);
        int d0 = 4*i + 2*(j&1);
        qq[i][j] = ((const u64*)g_qk)[b*256 + s*32 + (d0>>1)];
    }

    u64 acc[SS]; float dsum[SS];
    #pragma unroll
    for (int s = 0; s < SS; s++){ acc[s] = 0ull; dsum[s] = 0.f; }

    int base = b*NN + p*TOKPB;
    for (int c = 0; c < NCHUNK; c++){
        u64 xr[8];
        const u64* src = (const u64*)(g_x + (size_t)(base + c*CHUNK + 8*w)*64);
        #pragma unroll
        for (int j = 0; j < 8; j++) xr[j] = src[j*32 + lane];
        #pragma unroll
        for (int j = 0; j < 8; j++) *(u64*)&xs[8*w + j][2*lane] = xr[j];
        __syncthreads();

        if (tid < 128){
            int t = tid & 63, g = tid >> 6;
            u64 la0 = 0, la1 = 0, la2 = 0, la3 = 0;
            #pragma unroll
            for (int i = 0; i < 16; i++){
                ulonglong2 xv = *(const ulonglong2*)&xs[t][4*i];
                const ulonglong2* qp = (const ulonglong2*)&qq[i][8*g];
                ulonglong2 q0 = qp[0], q1 = qp[1], q2 = qp[2], q3 = qp[3];
                la0 = ffma2(xv.x, q0.x, la0); la0 = ffma2(xv.y, q0.y, la0);
                la1 = ffma2(xv.x, q1.x, la1); la1 = ffma2(xv.y, q1.y, la1);
                la2 = ffma2(xv.x, q2.x, la2); la2 = ffma2(xv.y, q2.y, la2);
                la3 = ffma2(xv.x, q3.x, la3); la3 = ffma2(xv.y, q3.y, la3);
            }
            float a, bq, l0, l1, l2, l3;
            up2(la0, a, bq); l0 = a + bq;
            up2(la1, a, bq); l1 = a + bq;
            up2(la2, a, bq); l2 = a + bq;
            up2(la3, a, bq); l3 = a + bq;
            *(float4*)&lgs[t][4*g] = make_float4(l0, l1, l2, l3);
        }
        __syncthreads();

        if (tid < 64){
            int t = tid;
            float4 A = *(const float4*)&lgs[t][0];
            float4 Bq = *(const float4*)&lgs[t][4];
            float lg[SS] = {A.x, A.y, A.z, A.w, Bq.x, Bq.y, Bq.z, Bq.w};
            float mx = -1e30f;
            #pragma unroll
            for (int s = 0; s < SS; s++) mx = fmaxf(mx, lg[s]);
            float sum = 0.f;
            #pragma unroll
            for (int s = 0; s < SS; s++){ lg[s] = __expf(lg[s]-mx); sum += lg[s]; }
            float inv = 1.f/sum;
            #pragma unroll
            for (int s = 0; s < SS; s++){
                lg[s] = lg[s]*inv + 1e-8f;
                dsum[s] += lg[s];
            }
            #pragma unroll
            for (int k = 0; k < 4; k++){
                ulonglong2 pr;
                pr.x = pk2(lg[2*k],   lg[2*k]);
                pr.y = pk2(lg[2*k+1], lg[2*k+1]);
                *(ulonglong2*)&ws2[t][2*k] = pr;
            }
            if (fin){
                float4* dst = (float4*)(out_w + (size_t)(base + c*CHUNK + t)*SS);
                dst[0] = make_float4(lg[0], lg[1], lg[2], lg[3]);
                dst[1] = make_float4(lg[4], lg[5], lg[6], lg[7]);
            }
        }
        __syncthreads();

        #pragma unroll
        for (int j = 0; j < 8; j++){
            int n = 8*w + j;
            ulonglong2 w0 = *(const ulonglong2*)&ws2[n][0];
            ulonglong2 w1p = *(const ulonglong2*)&ws2[n][2];
            ulonglong2 w2p = *(const ulonglong2*)&ws2[n][4];
            ulonglong2 w3p = *(const ulonglong2*)&ws2[n][6];
            u64 xv = xr[j];
            acc[0] = ffma2(xv, w0.x,  acc[0]);
            acc[1] = ffma2(xv, w0.y,  acc[1]);
            acc[2] = ffma2(xv, w1p.x, acc[2]);
            acc[3] = ffma2(xv, w1p.y, acc[3]);
            acc[4] = ffma2(xv, w2p.x, acc[4]);
            acc[5] = ffma2(xv, w2p.y, acc[5]);
            acc[6] = ffma2(xv, w3p.x, acc[6]);
            acc[7] = ffma2(xv, w3p.y, acc[7]);
        }
    }
    __syncthreads();

    float* red  = &xs[0][0];
    float* dred = &lgs[0][0];
    #pragma unroll
    for (int s = 0; s < SS; s++){
        float a, bq; up2(acc[s], a, bq);
        red[w*512 + s*64 + 2*lane]   = a;
        red[w*512 + s*64 + 2*lane+1] = bq;
    }
    if (tid < 64){
        #pragma unroll
        for (int s = 0; s < SS; s++) dred[s*64 + tid] = dsum[s];
    }
    __syncthreads();
    #pragma unroll
    for (int k = 0; k < 2; k++){
        int o = tid + k*256;
        float sum = 0.f;
        #pragma unroll
        for (int ww = 0; ww < 8; ww++) sum += red[ww*512 + o];
        g_prep[p*NROW*DD + b*512 + o] = sum;
    }
    if (tid < 8){
        float sum = 0.f;
        #pragma unroll
        for (int t2 = 0; t2 < 64; t2++) sum += dred[tid*64 + t2];
        g_denp[p*NROW + b*SS + tid] = sum;
    }
}

// ---------------- slot update: 256 threads/row ----------------
__global__ void __launch_bounds__(256) k_update(int init, int wout,
    const float* __restrict__ eps, const float* __restrict__ mu,
    const float* __restrict__ lv,
    const float* __restrict__ bih, const float* __restrict__ bhh,
    const float* __restrict__ nrw, const float* __restrict__ nrb,
    const float* __restrict__ b2,  const float* __restrict__ nsw,
    const float* __restrict__ nsb, const float* __restrict__ kw,
    float* __restrict__ out_slots){
    int r = blockIdx.x;
    int tid = threadIdx.x, d = tid & 63, q = tid >> 6;
    int lane = tid & 31, w = tid >> 5;
    __shared__ float av[64], hp[64], tt[64], mm[128];
    __shared__ float pp[4][144];
    __shared__ float pg[6][4][64];
    __shared__ float ps[8], pq2[8];
    float h2;
    if (!init){
        float den = 0.f;
        #pragma unroll
        for (int p = 0; p < NPART; p++) den += g_denp[p*NROW + r];
        float pre = 0.f;
        #pragma unroll
        for (int p = 0; p < NPART; p++) pre += g_prep[p*NROW*DD + r*64 + d];
        if (q == 0){ av[d] = pre/den; hp[d] = g_slots[r*64 + d]; }
        __syncthreads();
        float at = 0.f;
        #pragma unroll
        for (int e0 = 0; e0 < 16; e0++){
            int e = q*16 + e0;
            at += av[e]*g_vwT[e*64 + d];
        }
        pp[q][d] = at;
        __syncthreads();
        at = (pp[0][d]+pp[1][d]) + (pp[2][d]+pp[3][d]);
        __syncthreads();
        if (q == 0) av[d] = at;
        __syncthreads();
        float gr=0.f, gz=0.f, gn=0.f, hr=0.f, hz=0.f, hn=0.f;
        #pragma unroll
        for (int e0 = 0; e0 < 16; e0++){
            int e = q*16 + e0;
            float a = av[e], hpe = hp[e];
            const float* wi = &g_wihT[e*192];
            const float* wh = &g_whhT[e*192];
            gr += a*wi[d];      gz += a*wi[64+d];
            gn += a*wi[128+d];  hr += hpe*wh[d];
            hz += hpe*wh[64+d]; hn += hpe*wh[128+d];
        }
        pg[0][q][d]=gr; pg[1][q][d]=gz; pg[2][q][d]=gn;
        pg[3][q][d]=hr; pg[4][q][d]=hz; pg[5][q][d]=hn;
        __syncthreads();
        gr = bih[d]; gz = bih[64+d]; gn = bih[128+d];
        hr = bhh[d]; hz = bhh[64+d]; hn = bhh[128+d];
        #pragma unroll
        for (int k = 0; k < 4; k++){
            gr += pg[0][k][d]; gz += pg[1][k][d]; gn += pg[2][k][d];
            hr += pg[3][k][d]; hz += pg[4][k][d]; hn += pg[5][k][d];
        }
        float rg = 1.f/(1.f + __expf(-(gr+hr)));
        float zg = 1.f/(1.f + __expf(-(gz+hz)));
        float ng = tanhf(gn + rg*hn);
        float h = (1.f-zg)*ng + zg*hp[d];
        float s = h, qs = h*h;
        #pragma unroll
        for (int o = 16; o; o >>= 1){
            s  += __shfl_xor_sync(~0u, s,  o);
            qs += __shfl_xor_sync(~0u, qs, o);
        }
        if (lane == 0){ ps[w] = s; pq2[w] = qs; }
        __syncthreads();
        int wb = w & ~1;
        s = ps[wb] + ps[wb+1]; qs = pq2[wb] + pq2[wb+1];
        float m = s*(1.f/64.f);
        float rs = rsqrtf(qs*(1.f/64.f) - m*m + 1e-5f);
        float ttv = (h-m)*rs*nrw[d] + nrb[d];
        __syncthreads();
        if (q == 0) tt[d] = ttv;
        __syncthreads();
        int j = tid & 127, hq = tid >> 7;
        float m1 = 0.f;
        #pragma unroll
        for (int e0 = 0; e0 < 32; e0++){
            int e = hq*32 + e0;
            m1 += tt[e]*g_w1T[e*128 + j];
        }
        pp[hq][j] = m1;
        __syncthreads();
        if (hq == 0) mm[j] = fmaxf(pp[0][j] + pp[1][j], 0.f);
        __syncthreads();
        float o2 = 0.f;
        #pragma unroll
        for (int j0 = 0; j0 < 32; j0++){
            int jj = q*32 + j0;
            o2 += mm[jj]*g_w2T[jj*64 + d];
        }
        pp[q][d] = o2;
        __syncthreads();
        h2 = h + b2[d] + (pp[0][d]+pp[1][d]) + (pp[2][d]+pp[3][d]);
        __syncthreads();
    } else {
        h2 = mu[d] + __expf(0.5f*lv[d])*eps[r*64 + d];
    }
    if (q == 0){
        g_slots[r*64 + d] = h2;
        if (wout) out_slots[r*64 + d] = h2;
    }
    float s2 = h2, q2s = h2*h2;
    #pragma unroll
    for (int o = 16; o; o >>= 1){
        s2  += __shfl_xor_sync(~0u, s2,  o);
        q2s += __shfl_xor_sync(~0u, q2s, o);
    }
    if (lane == 0){ ps[w] = s2; pq2[w] = q2s; }
    __syncthreads();
    int wb2 = w & ~1;
    s2 = ps[wb2] + ps[wb2+1]; q2s = pq2[wb2] + pq2[wb2+1];
    float m2 = s2*(1.f/64.f);
    float rs2 = rsqrtf(q2s*(1.f/64.f) - m2*m2 + 1e-5f);
    float ttv2 = (h2-m2)*rs2*nsw[d] + nsb[d];
    __syncthreads();
    if (q == 0) tt[d] = ttv2;
    __syncthreads();
    float qd = 0.f;
    #pragma unroll
    for (int e0 = 0; e0 < 16; e0++){
        int e = q*16 + e0;
        qd += tt[e]*g_qwT[e*64 + d];
    }
    pp[q][d] = qd;
    __syncthreads();
    float qv = (pp[0][d]+pp[1][d]) + (pp[2][d]+pp[3][d]);
    __syncthreads();
    if (q == 0) av[d] = qv;
    __syncthreads();
    float qk = 0.f;
    #pragma unroll
    for (int e0 = 0; e0 < 16; e0++){
        int e = q*16 + e0;
        qk += av[e]*kw[e*64 + d];
    }
    pp[q][d] = qk;
    __syncthreads();
    if (q == 0)
        g_qk[r*64 + d] = 0.125f*((pp[0][d]+pp[1][d]) + (pp[2][d]+pp[3][d]));
}

// ---------------- w = what / denom (self-computed from g_denp) -------------
__global__ void __launch_bounds__(256) k_wnorm(float* __restrict__ out_w){
    __shared__ float invd[8];
    int tok = blockIdx.x*256 + threadIdx.x;
    int b = tok >> 12;
    if (threadIdx.x < 8){
        float den = 0.f;
        #pragma unroll
        for (int p = 0; p < NPART; p++) den += g_denp[p*NROW + b*SS + threadIdx.x];
        invd[threadIdx.x] = 1.f/den;
    }
    __syncthreads();
    float4* pw = (float4*)(out_w + (size_t)tok*SS);
    float4 a = pw[0], c = pw[1];
    a.x *= invd[0]; a.y *= invd[1]; a.z *= invd[2]; a.w *= invd[3];
    c.x *= invd[4]; c.y *= invd[5]; c.z *= invd[6]; c.w *= invd[7];
    pw[0] = a; pw[1] = c;
}

extern "C" void kernel_launch(void* const* d_in, const int* in_sizes, int n_in,
                              void* d_out, int out_size){
    const float* inp = (const float*)d_in[0];
    const float* eps = (const float*)d_in[1];
    const float* mu  = (const float*)d_in[2];
    const float* lv  = (const float*)d_in[3];
    const float* kw  = (const float*)d_in[4];
    const float* vw  = (const float*)d_in[5];
    const float* qw  = (const float*)d_in[6];
    const float* niw = (const float*)d_in[7];
    const float* nib = (const float*)d_in[8];
    const float* nsw = (const float*)d_in[9];
    const float* nsb = (const float*)d_in[10];
    const float* nrw = (const float*)d_in[11];
    const float* nrb = (const float*)d_in[12];
    const float* wih = (const float*)d_in[13];
    const float* whh = (const float*)d_in[14];
    const float* bih = (const float*)d_in[15];
    const float* bhh = (const float*)d_in[16];
    const float* w1  = (const float*)d_in[17];
    const float* w2  = (const float*)d_in[18];
    const float* b2  = (const float*)d_in[19];
    float* out_slots = (float*)d_out;
    float* out_w     = out_slots + NROW*DD;
    cudaStream_t s0 = 0;

    k_tr<<<192, 256>>>(vw, wih, whh, w1, w2, qw);
    // fork: slot init (needs only k_tr) runs beside k_prep
    cudaEventRecord(g_hx.e_tr, s0);
    cudaStreamWaitEvent(g_hx.s1, g_hx.e_tr, 0);
    k_update<<<NROW, 256, 0, g_hx.s1>>>(1, 0, eps, mu, lv, bih, bhh,
                                        nrw, nrb, b2, nsw, nsb, kw, out_slots);
    cudaEventRecord(g_hx.e_init, g_hx.s1);
    k_prep<<<2048, 256>>>(inp, niw, nib);
    cudaStreamWaitEvent(s0, g_hx.e_init, 0);

    for (int step = 0; step < 4; step++){
        int fin = (step == 3);
        k_attn<<<dim3(NPART, BB), 256>>>(fin, out_w);
        if (fin){
            // fork: w-normalization (needs only k_attn) runs beside final update
            cudaEventRecord(g_hx.e_attn, s0);
            cudaStreamWaitEvent(g_hx.s1, g_hx.e_attn, 0);
            k_wnorm<<<NTOK/256, 256, 0, g_hx.s1>>>(out_w);
            cudaEventRecord(g_hx.e_wn, g_hx.s1);
        }
        k_update<<<NROW, 256>>>(0, fin, eps, mu, lv, bih, bhh,
                                nrw, nrb, b2, nsw, nsb, kw, out_slots);
    }
    cudaStreamWaitEvent(s0, g_hx.e_wn, 0);
}

// round 16
// speedup vs baseline: 1.0321x; 1.0321x over previous
#include <cuda_runtime.h>
#include <cuda_bf16.h>

#define BB 128
#define NN 4096
#define SS 8
#define DD 64
#define NTOK (BB*NN)
#define NPART 16
#define TOKPB (NN/NPART)
#define CHUNK 64
#define NCHUNK (TOKPB/CHUNK)
#define NROW (BB*SS)

__device__ float g_x[NTOK*DD];
__device__ float g_prep[NPART*NROW*DD];
__device__ float g_denp[NPART*NROW];
__device__ float g_qk[NROW*DD];
__device__ float g_slots[NROW*DD];
__device__ float g_dent[NROW];

__device__ float g_vwT[64*64];
__device__ float g_wihT[64*192];
__device__ float g_whhT[64*192];
__device__ float g_w1T[64*128];
__device__ float g_w2T[128*64];
__device__ float g_qwT[64*64];

typedef unsigned long long u64;
__device__ __forceinline__ u64 pk2(float x, float y){
    u64 r; asm("mov.b64 %0,{%1,%2};" : "=l"(r) : "f"(x), "f"(y)); return r;
}
__device__ __forceinline__ void up2(u64 v, float &x, float &y){
    asm("mov.b64 {%0,%1},%2;" : "=f"(x), "=f"(y) : "l"(v));
}
__device__ __forceinline__ u64 ffma2(u64 a, u64 b, u64 c){
    u64 d; asm("fma.rn.f32x2 %0,%1,%2,%3;" : "=l"(d) : "l"(a), "l"(b), "l"(c)); return d;
}

// ---------------- fused: LayerNorm(inputs) + weight transpose --------------
// blocks [0,2048): 4-token-ILP LayerNorm; blocks [2048,2240): transpose.
__global__ void k_prep(const float* __restrict__ inp,
                       const float* __restrict__ nw,
                       const float* __restrict__ nb,
                       const float* __restrict__ vw, const float* __restrict__ wih,
                       const float* __restrict__ whh, const float* __restrict__ w1,
                       const float* __restrict__ w2,  const float* __restrict__ qw){
    if (blockIdx.x >= 2048){
        int i = (blockIdx.x - 2048)*256 + threadIdx.x;
        if (i < 4096){
            g_vwT[(i&63)*64 + (i>>6)] = vw[i];
        } else if (i < 16384){
            int j = i - 4096;  g_wihT[(j&63)*192 + (j>>6)] = wih[j];
        } else if (i < 28672){
            int j = i - 16384; g_whhT[(j&63)*192 + (j>>6)] = whh[j];
        } else if (i < 36864){
            int j = i - 28672; g_w1T[(j&63)*128 + (j>>6)] = w1[j];
        } else if (i < 45056){
            int j = i - 36864; g_w2T[(j&127)*64 + (j>>7)] = w2[j];
        } else if (i < 49152){
            int j = i - 45056; g_qwT[(j&63)*64 + (j>>6)] = qw[j];
        }
        return;
    }
    int gw = (blockIdx.x*blockDim.x + threadIdx.x) >> 5;
    int lane = threadIdx.x & 31;
    int nwarp = (2048*blockDim.x) >> 5;
    float2 wv = ((const float2*)nw)[lane];
    float2 bv = ((const float2*)nb)[lane];
    for (int t0 = gw*4; t0 < NTOK; t0 += nwarp*4){
        float2 v[4];
        #pragma unroll
        for (int j = 0; j < 4; j++)
            v[j] = ((const float2*)inp)[(size_t)(t0+j)*32 + lane];
        float s[4], q[4];
        #pragma unroll
        for (int j = 0; j < 4; j++){
            s[j] = v[j].x + v[j].y;
            q[j] = v[j].x*v[j].x + v[j].y*v[j].y;
        }
        #pragma unroll
        for (int o = 16; o; o >>= 1){
            #pragma unroll
            for (int j = 0; j < 4; j++){
                s[j] += __shfl_xor_sync(~0u, s[j], o);
                q[j] += __shfl_xor_sync(~0u, q[j], o);
            }
        }
        #pragma unroll
        for (int j = 0; j < 4; j++){
            float m = s[j]*(1.f/64.f);
            float rs = rsqrtf(q[j]*(1.f/64.f) - m*m + 1e-5f);
            float2 o2;
            o2.x = (v[j].x-m)*rs*wv.x + bv.x;
            o2.y = (v[j].y-m)*rs*wv.y + bv.y;
            ((float2*)g_x)[(size_t)(t0+j)*32 + lane] = o2;
        }
    }
}

// ---------------- attention accumulation, grid (16 parts, 128 batch) -------
__global__ void __launch_bounds__(256, 3) k_attn(int fin, float* __restrict__ out_w){
    int p = blockIdx.x, b = blockIdx.y;
    int tid = threadIdx.x, lane = tid & 31, w = tid >> 5;
    __shared__ float xs[CHUNK][68];
    __shared__ u64  ws2[CHUNK][10];
    __shared__ float lgs[CHUNK][12];
    __shared__ u64  qq[16][16];

    {
        int i = tid >> 4, j = tid & 15;
        int s = 4*(j>>3) + ((j>>1)&3);
        int d0 = 4*i + 2*(j&1);
        qq[i][j] = ((const u64*)g_qk)[b*256 + s*32 + (d0>>1)];
    }

    u64 acc[SS]; float dsum[SS];
    #pragma unroll
    for (int s = 0; s < SS; s++){ acc[s] = 0ull; dsum[s] = 0.f; }

    int base = b*NN + p*TOKPB;
    for (int c = 0; c < NCHUNK; c++){
        u64 xr[8];
        const u64* src = (const u64*)(g_x + (size_t)(base + c*CHUNK + 8*w)*64);
        #pragma unroll
        for (int j = 0; j < 8; j++) xr[j] = src[j*32 + lane];
        #pragma unroll
        for (int j = 0; j < 8; j++) *(u64*)&xs[8*w + j][2*lane] = xr[j];
        __syncthreads();

        if (tid < 128){
            int t = tid & 63, g = tid >> 6;
            u64 la0 = 0, la1 = 0, la2 = 0, la3 = 0;
            #pragma unroll
            for (int i = 0; i < 16; i++){
                ulonglong2 xv = *(const ulonglong2*)&xs[t][4*i];
                const ulonglong2* qp = (const ulonglong2*)&qq[i][8*g];
                ulonglong2 q0 = qp[0], q1 = qp[1], q2 = qp[2], q3 = qp[3];
                la0 = ffma2(xv.x, q0.x, la0); la0 = ffma2(xv.y, q0.y, la0);
                la1 = ffma2(xv.x, q1.x, la1); la1 = ffma2(xv.y, q1.y, la1);
                la2 = ffma2(xv.x, q2.x, la2); la2 = ffma2(xv.y, q2.y, la2);
                la3 = ffma2(xv.x, q3.x, la3); la3 = ffma2(xv.y, q3.y, la3);
            }
            float a, bq, l0, l1, l2, l3;
            up2(la0, a, bq); l0 = a + bq;
            up2(la1, a, bq); l1 = a + bq;
            up2(la2, a, bq); l2 = a + bq;
            up2(la3, a, bq); l3 = a + bq;
            *(float4*)&lgs[t][4*g] = make_float4(l0, l1, l2, l3);
        }
        __syncthreads();

        if (tid < 64){
            int t = tid;
            float4 A = *(const float4*)&lgs[t][0];
            float4 Bq = *(const float4*)&lgs[t][4];
            float lg[SS] = {A.x, A.y, A.z, A.w, Bq.x, Bq.y, Bq.z, Bq.w};
            float mx = -1e30f;
            #pragma unroll
            for (int s = 0; s < SS; s++) mx = fmaxf(mx, lg[s]);
            float sum = 0.f;
            #pragma unroll
            for (int s = 0; s < SS; s++){ lg[s] = __expf(lg[s]-mx); sum += lg[s]; }
            float inv = 1.f/sum;
            #pragma unroll
            for (int s = 0; s < SS; s++){
                lg[s] = lg[s]*inv + 1e-8f;
                dsum[s] += lg[s];
            }
            #pragma unroll
            for (int k = 0; k < 4; k++){
                ulonglong2 pr;
                pr.x = pk2(lg[2*k],   lg[2*k]);
                pr.y = pk2(lg[2*k+1], lg[2*k+1]);
                *(ulonglong2*)&ws2[t][2*k] = pr;
            }
            if (fin){
                float4* dst = (float4*)(out_w + (size_t)(base + c*CHUNK + t)*SS);
                dst[0] = make_float4(lg[0], lg[1], lg[2], lg[3]);
                dst[1] = make_float4(lg[4], lg[5], lg[6], lg[7]);
            }
        }
        __syncthreads();

        #pragma unroll
        for (int j = 0; j < 8; j++){
            int n = 8*w + j;
            ulonglong2 w0 = *(const ulonglong2*)&ws2[n][0];
            ulonglong2 w1p = *(const ulonglong2*)&ws2[n][2];
            ulonglong2 w2p = *(const ulonglong2*)&ws2[n][4];
            ulonglong2 w3p = *(const ulonglong2*)&ws2[n][6];
            u64 xv = xr[j];
            acc[0] = ffma2(xv, w0.x,  acc[0]);
            acc[1] = ffma2(xv, w0.y,  acc[1]);
            acc[2] = ffma2(xv, w1p.x, acc[2]);
            acc[3] = ffma2(xv, w1p.y, acc[3]);
            acc[4] = ffma2(xv, w2p.x, acc[4]);
            acc[5] = ffma2(xv, w2p.y, acc[5]);
            acc[6] = ffma2(xv, w3p.x, acc[6]);
            acc[7] = ffma2(xv, w3p.y, acc[7]);
        }
    }
    __syncthreads();

    float* red  = &xs[0][0];
    float* dred = &lgs[0][0];
    #pragma unroll
    for (int s = 0; s < SS; s++){
        float a, bq; up2(acc[s], a, bq);
        red[w*512 + s*64 + 2*lane]   = a;
        red[w*512 + s*64 + 2*lane+1] = bq;
    }
    if (tid < 64){
        #pragma unroll
        for (int s = 0; s < SS; s++) dred[s*64 + tid] = dsum[s];
    }
    __syncthreads();
    #pragma unroll
    for (int k = 0; k < 2; k++){
        int o = tid + k*256;
        float sum = 0.f;
        #pragma unroll
        for (int ww = 0; ww < 8; ww++) sum += red[ww*512 + o];
        g_prep[p*NROW*DD + b*512 + o] = sum;
    }
    if (tid < 8){
        float sum = 0.f;
        #pragma unroll
        for (int t2 = 0; t2 < 64; t2++) sum += dred[tid*64 + t2];
        g_denp[p*NROW + b*SS + tid] = sum;
    }
}

// ---------------- slot update: 256 threads/row ----------------
__global__ void __launch_bounds__(256) k_update(int init, int wout,
    const float* __restrict__ eps, const float* __restrict__ mu,
    const float* __restrict__ lv,
    const float* __restrict__ bih, const float* __restrict__ bhh,
    const float* __restrict__ nrw, const float* __restrict__ nrb,
    const float* __restrict__ b2,  const float* __restrict__ nsw,
    const float* __restrict__ nsb, const float* __restrict__ kw,
    float* __restrict__ out_slots){
    int r = blockIdx.x;
    int tid = threadIdx.x, d = tid & 63, q = tid >> 6;
    int lane = tid & 31, w = tid >> 5;
    __shared__ float av[64], hp[64], tt[64], mm[128];
    __shared__ float pp[4][144];
    __shared__ float pg[6][4][64];
    __shared__ float ps[8], pq2[8];
    float h2;
    if (!init){
        float den = 0.f;
        #pragma unroll
        for (int p = 0; p < NPART; p++) den += g_denp[p*NROW + r];
        if (tid == 0 && wout) g_dent[r] = den;
        float pre = 0.f;
        #pragma unroll
        for (int p = 0; p < NPART; p++) pre += g_prep[p*NROW*DD + r*64 + d];
        if (q == 0){ av[d] = pre/den; hp[d] = g_slots[r*64 + d]; }
        __syncthreads();
        float at = 0.f;
        #pragma unroll
        for (int e0 = 0; e0 < 16; e0++){
            int e = q*16 + e0;
            at += av[e]*g_vwT[e*64 + d];
        }
        pp[q][d] = at;
        __syncthreads();
        at = (pp[0][d]+pp[1][d]) + (pp[2][d]+pp[3][d]);
        __syncthreads();
        if (q == 0) av[d] = at;
        __syncthreads();
        float gr=0.f, gz=0.f, gn=0.f, hr=0.f, hz=0.f, hn=0.f;
        #pragma unroll
        for (int e0 = 0; e0 < 16; e0++){
            int e = q*16 + e0;
            float a = av[e], hpe = hp[e];
            const float* wi = &g_wihT[e*192];
            const float* wh = &g_whhT[e*192];
            gr += a*wi[d];      gz += a*wi[64+d];
            gn += a*wi[128+d];  hr += hpe*wh[d];
            hz += hpe*wh[64+d]; hn += hpe*wh[128+d];
        }
        pg[0][q][d]=gr; pg[1][q][d]=gz; pg[2][q][d]=gn;
        pg[3][q][d]=hr; pg[4][q][d]=hz; pg[5][q][d]=hn;
        __syncthreads();
        gr = bih[d]; gz = bih[64+d]; gn = bih[128+d];
        hr = bhh[d]; hz = bhh[64+d]; hn = bhh[128+d];
        #pragma unroll
        for (int k = 0; k < 4; k++){
            gr += pg[0][k][d]; gz += pg[1][k][d]; gn += pg[2][k][d];
            hr += pg[3][k][d]; hz += pg[4][k][d]; hn += pg[5][k][d];
        }
        float rg = 1.f/(1.f + __expf(-(gr+hr)));
        float zg = 1.f/(1.f + __expf(-(gz+hz)));
        float ng = tanhf(gn + rg*hn);
        float h = (1.f-zg)*ng + zg*hp[d];
        float s = h, qs = h*h;
        #pragma unroll
        for (int o = 16; o; o >>= 1){
            s  += __shfl_xor_sync(~0u, s,  o);
            qs += __shfl_xor_sync(~0u, qs, o);
        }
        if (lane == 0){ ps[w] = s; pq2[w] = qs; }
        __syncthreads();
        int wb = w & ~1;
        s = ps[wb] + ps[wb+1]; qs = pq2[wb] + pq2[wb+1];
        float m = s*(1.f/64.f);
        float rs = rsqrtf(qs*(1.f/64.f) - m*m + 1e-5f);
        float ttv = (h-m)*rs*nrw[d] + nrb[d];
        __syncthreads();
        if (q == 0) tt[d] = ttv;
        __syncthreads();
        int j = tid & 127, hq = tid >> 7;
        float m1 = 0.f;
        #pragma unroll
        for (int e0 = 0; e0 < 32; e0++){
            int e = hq*32 + e0;
            m1 += tt[e]*g_w1T[e*128 + j];
        }
        pp[hq][j] = m1;
        __syncthreads();
        if (hq == 0) mm[j] = fmaxf(pp[0][j] + pp[1][j], 0.f);
        __syncthreads();
        float o2 = 0.f;
        #pragma unroll
        for (int j0 = 0; j0 < 32; j0++){
            int jj = q*32 + j0;
            o2 += mm[jj]*g_w2T[jj*64 + d];
        }
        pp[q][d] = o2;
        __syncthreads();
        h2 = h + b2[d] + (pp[0][d]+pp[1][d]) + (pp[2][d]+pp[3][d]);
        __syncthreads();
    } else {
        h2 = mu[d] + __expf(0.5f*lv[d])*eps[r*64 + d];
    }
    if (q == 0){
        g_slots[r*64 + d] = h2;
        if (wout) out_slots[r*64 + d] = h2;
    }
    float s2 = h2, q2s = h2*h2;
    #pragma unroll
    for (int o = 16; o; o >>= 1){
        s2  += __shfl_xor_sync(~0u, s2,  o);
        q2s += __shfl_xor_sync(~0u, q2s, o);
    }
    if (lane == 0){ ps[w] = s2; pq2[w] = q2s; }
    __syncthreads();
    int wb2 = w & ~1;
    s2 = ps[wb2] + ps[wb2+1]; q2s = pq2[wb2] + pq2[wb2+1];
    float m2 = s2*(1.f/64.f);
    float rs2 = rsqrtf(q2s*(1.f/64.f) - m2*m2 + 1e-5f);
    float ttv2 = (h2-m2)*rs2*nsw[d] + nsb[d];
    __syncthreads();
    if (q == 0) tt[d] = ttv2;
    __syncthreads();
    float qd = 0.f;
    #pragma unroll
    for (int e0 = 0; e0 < 16; e0++){
        int e = q*16 + e0;
        qd += tt[e]*g_qwT[e*64 + d];
    }
    pp[q][d] = qd;
    __syncthreads();
    float qv = (pp[0][d]+pp[1][d]) + (pp[2][d]+pp[3][d]);
    __syncthreads();
    if (q == 0) av[d] = qv;
    __syncthreads();
    float qk = 0.f;
    #pragma unroll
    for (int e0 = 0; e0 < 16; e0++){
        int e = q*16 + e0;
        qk += av[e]*kw[e*64 + d];
    }
    pp[q][d] = qk;
    __syncthreads();
    if (q == 0)
        g_qk[r*64 + d] = 0.125f*((pp[0][d]+pp[1][d]) + (pp[2][d]+pp[3][d]));
}

// ---------------- w = what / denom ----------------
__global__ void __launch_bounds__(256) k_wnorm(float* __restrict__ out_w){
    __shared__ float invd[8];
    int tok = blockIdx.x*256 + threadIdx.x;
    int b = tok >> 12;
    if (threadIdx.x < 8) invd[threadIdx.x] = 1.f/g_dent[b*SS + threadIdx.x];
    __syncthreads();
    float4* pw = (float4*)(out_w + (size_t)tok*SS);
    float4 a = pw[0], c = pw[1];
    a.x *= invd[0]; a.y *= invd[1]; a.z *= invd[2]; a.w *= invd[3];
    c.x *= invd[4]; c.y *= invd[5]; c.z *= invd[6]; c.w *= invd[7];
    pw[0] = a; pw[1] = c;
}

extern "C" void kernel_launch(void* const* d_in, const int* in_sizes, int n_in,
                              void* d_out, int out_size){
    const float* inp = (const float*)d_in[0];
    const float* eps = (const float*)d_in[1];
    const float* mu  = (const float*)d_in[2];
    const float* lv  = (const float*)d_in[3];
    const float* kw  = (const float*)d_in[4];
    const float* vw  = (const float*)d_in[5];
    const float* qw  = (const float*)d_in[6];
    const float* niw = (const float*)d_in[7];
    const float* nib = (const float*)d_in[8];
    const float* nsw = (const float*)d_in[9];
    const float* nsb = (const float*)d_in[10];
    const float* nrw = (const float*)d_in[11];
    const float* nrb = (const float*)d_in[12];
    const float* wih = (const float*)d_in[13];
    const float* whh = (const float*)d_in[14];
    const float* bih = (const float*)d_in[15];
    const float* bhh = (const float*)d_in[16];
    const float* w1  = (const float*)d_in[17];
    const float* w2  = (const float*)d_in[18];
    const float* b2  = (const float*)d_in[19];
    float* out_slots = (float*)d_out;
    float* out_w     = out_slots + NROW*DD;

    k_prep<<<2240, 256>>>(inp, niw, nib, vw, wih, whh, w1, w2, qw);
    k_update<<<NROW, 256>>>(1, 0, eps, mu, lv, bih, bhh,
                            nrw, nrb, b2, nsw, nsb, kw, out_slots);
    for (int step = 0; step < 4; step++){
        int fin = (step == 3);
        k_attn<<<dim3(NPART, BB), 256>>>(fin, out_w);
        k_update<<<NROW, 256>>>(0, fin, eps, mu, lv, bih, bhh,
                                nrw, nrb, b2, nsw, nsb, kw, out_slots);
    }
    k_wnorm<<<NTOK/256, 256>>>(out_w);
}

// round 17
// speedup vs baseline: 1.0651x; 1.0320x over previous
#include <cuda_runtime.h>
#include <cuda_bf16.h>

#define BB 128
#define NN 4096
#define SS 8
#define DD 64
#define NTOK (BB*NN)
#define NPART 16
#define TOKPB (NN/NPART)
#define CHUNK 64
#define NCHUNK (TOKPB/CHUNK)
#define NROW (BB*SS)

__device__ float g_x[NTOK*DD];
__device__ float g_prep[NPART*NROW*DD];
__device__ float g_denp[NPART*NROW];
__device__ float g_qk[NROW*DD];
__device__ float g_slots[NROW*DD];
__device__ float g_dent[NROW];

// float4-packed weights: W4[e4*J + j] = {W[4e4][j], W[4e4+1][j], W[4e4+2][j], W[4e4+3][j]}
__device__ float4 g_vw4[16*64];
__device__ float4 g_wih4[16*192];
__device__ float4 g_whh4[16*192];
__device__ float4 g_w14[16*128];
__device__ float4 g_w24[32*64];
__device__ float4 g_qw4[16*64];
__device__ float4 g_kw4[16*64];

typedef unsigned long long u64;
__device__ __forceinline__ u64 pk2(float x, float y){
    u64 r; asm("mov.b64 %0,{%1,%2};" : "=l"(r) : "f"(x), "f"(y)); return r;
}
__device__ __forceinline__ void up2(u64 v, float &x, float &y){
    asm("mov.b64 {%0,%1},%2;" : "=f"(x), "=f"(y) : "l"(v));
}
__device__ __forceinline__ u64 ffma2(u64 a, u64 b, u64 c){
    u64 d; asm("fma.rn.f32x2 %0,%1,%2,%3;" : "=l"(d) : "l"(a), "l"(b), "l"(c)); return d;
}

#define DOT4(acc, a4, w4) do { \
    acc += (a4).x*(w4).x; acc += (a4).y*(w4).y; \
    acc += (a4).z*(w4).z; acc += (a4).w*(w4).w; } while(0)

// ---------------- fused: LayerNorm(inputs) + weight packing ----------------
// blocks [0,2048): 4-token-ILP LayerNorm; blocks [2048,2256): pack weights.
__global__ void k_prep(const float* __restrict__ inp,
                       const float* __restrict__ nw,
                       const float* __restrict__ nb,
                       const float* __restrict__ vw, const float* __restrict__ wih,
                       const float* __restrict__ whh, const float* __restrict__ w1,
                       const float* __restrict__ w2,  const float* __restrict__ qw,
                       const float* __restrict__ kw){
    if (blockIdx.x >= 2048){
        int i = (blockIdx.x - 2048)*256 + threadIdx.x;   // 0..53247
        if (i < 4096){                                    // vw: [d][e]
            int d = i >> 6, e = i & 63;
            ((float*)g_vw4)[(((e>>2)*64) + d)*4 + (e&3)] = vw[i];
        } else if (i < 16384){                            // wih: [j][e]
            int j0 = i - 4096; int j = j0 >> 6, e = j0 & 63;
            ((float*)g_wih4)[(((e>>2)*192) + j)*4 + (e&3)] = wih[j0];
        } else if (i < 28672){                            // whh
            int j0 = i - 16384; int j = j0 >> 6, e = j0 & 63;
            ((float*)g_whh4)[(((e>>2)*192) + j)*4 + (e&3)] = whh[j0];
        } else if (i < 36864){                            // w1: [j][e]
            int j0 = i - 28672; int j = j0 >> 6, e = j0 & 63;
            ((float*)g_w14)[(((e>>2)*128) + j)*4 + (e&3)] = w1[j0];
        } else if (i < 45056){                            // w2: [d][j]
            int j0 = i - 36864; int d = j0 >> 7, j = j0 & 127;
            ((float*)g_w24)[(((j>>2)*64) + d)*4 + (j&3)] = w2[j0];
        } else if (i < 49152){                            // qw: [d][e]
            int j0 = i - 45056; int d = j0 >> 6, e = j0 & 63;
            ((float*)g_qw4)[(((e>>2)*64) + d)*4 + (e&3)] = qw[j0];
        } else {                                          // kw: [e][d]
            int j0 = i - 49152; int e = j0 >> 6, d = j0 & 63;
            ((float*)g_kw4)[(((e>>2)*64) + d)*4 + (e&3)] = kw[j0];
        }
        return;
    }
    int gw = (blockIdx.x*blockDim.x + threadIdx.x) >> 5;
    int lane = threadIdx.x & 31;
    int nwarp = (2048*blockDim.x) >> 5;
    float2 wv = ((const float2*)nw)[lane];
    float2 bv = ((const float2*)nb)[lane];
    for (int t0 = gw*4; t0 < NTOK; t0 += nwarp*4){
        float2 v[4];
        #pragma unroll
        for (int j = 0; j < 4; j++)
            v[j] = ((const float2*)inp)[(size_t)(t0+j)*32 + lane];
        float s[4], q[4];
        #pragma unroll
        for (int j = 0; j < 4; j++){
            s[j] = v[j].x + v[j].y;
            q[j] = v[j].x*v[j].x + v[j].y*v[j].y;
        }
        #pragma unroll
        for (int o = 16; o; o >>= 1){
            #pragma unroll
            for (int j = 0; j < 4; j++){
                s[j] += __shfl_xor_sync(~0u, s[j], o);
                q[j] += __shfl_xor_sync(~0u, q[j], o);
            }
        }
        #pragma unroll
        for (int j = 0; j < 4; j++){
            float m = s[j]*(1.f/64.f);
            float rs = rsqrtf(q[j]*(1.f/64.f) - m*m + 1e-5f);
            float2 o2;
            o2.x = (v[j].x-m)*rs*wv.x + bv.x;
            o2.y = (v[j].y-m)*rs*wv.y + bv.y;
            ((float2*)g_x)[(size_t)(t0+j)*32 + lane] = o2;
        }
    }
}

// ---------------- attention accumulation, grid (16 parts, 128 batch) -------
__global__ void __launch_bounds__(256, 3) k_attn(int fin, float* __restrict__ out_w){
    int p = blockIdx.x, b = blockIdx.y;
    int tid = threadIdx.x, lane = tid & 31, w = tid >> 5;
    __shared__ float xs[CHUNK][68];
    __shared__ u64  ws2[CHUNK][10];
    __shared__ float lgs[CHUNK][12];
    __shared__ u64  qq[16][16];

    {
        int i = tid >> 4, j = tid & 15;
        int s = 4*(j>>3) + ((j>>1)&3);
        int d0 = 4*i + 2*(j&1);
        qq[i][j] = ((const u64*)g_qk)[b*256 + s*32 + (d0>>1)];
    }

    u64 acc[SS]; float dsum[SS];
    #pragma unroll
    for (int s = 0; s < SS; s++){ acc[s] = 0ull; dsum[s] = 0.f; }

    int base = b*NN + p*TOKPB;
    for (int c = 0; c < NCHUNK; c++){
        u64 xr[8];
        const u64* src = (const u64*)(g_x + (size_t)(base + c*CHUNK + 8*w)*64);
        #pragma unroll
        for (int j = 0; j < 8; j++) xr[j] = src[j*32 + lane];
        #pragma unroll
        for (int j = 0; j < 8; j++) *(u64*)&xs[8*w + j][2*lane] = xr[j];
        __syncthreads();

        if (tid < 128){
            int t = tid & 63, g = tid >> 6;
            u64 la0 = 0, la1 = 0, la2 = 0, la3 = 0;
            #pragma unroll
            for (int i = 0; i < 16; i++){
                ulonglong2 xv = *(const ulonglong2*)&xs[t][4*i];
                const ulonglong2* qp = (const ulonglong2*)&qq[i][8*g];
                ulonglong2 q0 = qp[0], q1 = qp[1], q2 = qp[2], q3 = qp[3];
                la0 = ffma2(xv.x, q0.x, la0); la0 = ffma2(xv.y, q0.y, la0);
                la1 = ffma2(xv.x, q1.x, la1); la1 = ffma2(xv.y, q1.y, la1);
                la2 = ffma2(xv.x, q2.x, la2); la2 = ffma2(xv.y, q2.y, la2);
                la3 = ffma2(xv.x, q3.x, la3); la3 = ffma2(xv.y, q3.y, la3);
            }
            float a, bq, l0, l1, l2, l3;
            up2(la0, a, bq); l0 = a + bq;
            up2(la1, a, bq); l1 = a + bq;
            up2(la2, a, bq); l2 = a + bq;
            up2(la3, a, bq); l3 = a + bq;
            *(float4*)&lgs[t][4*g] = make_float4(l0, l1, l2, l3);
        }
        __syncthreads();

        if (tid < 64){
            int t = tid;
            float4 A = *(const float4*)&lgs[t][0];
            float4 Bq = *(const float4*)&lgs[t][4];
            float lg[SS] = {A.x, A.y, A.z, A.w, Bq.x, Bq.y, Bq.z, Bq.w};
            float mx = -1e30f;
            #pragma unroll
            for (int s = 0; s < SS; s++) mx = fmaxf(mx, lg[s]);
            float sum = 0.f;
            #pragma unroll
            for (int s = 0; s < SS; s++){ lg[s] = __expf(lg[s]-mx); sum += lg[s]; }
            float inv = 1.f/sum;
            #pragma unroll
            for (int s = 0; s < SS; s++){
                lg[s] = lg[s]*inv + 1e-8f;
                dsum[s] += lg[s];
            }
            #pragma unroll
            for (int k = 0; k < 4; k++){
                ulonglong2 pr;
                pr.x = pk2(lg[2*k],   lg[2*k]);
                pr.y = pk2(lg[2*k+1], lg[2*k+1]);
                *(ulonglong2*)&ws2[t][2*k] = pr;
            }
            if (fin){
                float4* dst = (float4*)(out_w + (size_t)(base + c*CHUNK + t)*SS);
                dst[0] = make_float4(lg[0], lg[1], lg[2], lg[3]);
                dst[1] = make_float4(lg[4], lg[5], lg[6], lg[7]);
            }
        }
        __syncthreads();

        #pragma unroll
        for (int j = 0; j < 8; j++){
            int n = 8*w + j;
            ulonglong2 w0 = *(const ulonglong2*)&ws2[n][0];
            ulonglong2 w1p = *(const ulonglong2*)&ws2[n][2];
            ulonglong2 w2p = *(const ulonglong2*)&ws2[n][4];
            ulonglong2 w3p = *(const ulonglong2*)&ws2[n][6];
            u64 xv = xr[j];
            acc[0] = ffma2(xv, w0.x,  acc[0]);
            acc[1] = ffma2(xv, w0.y,  acc[1]);
            acc[2] = ffma2(xv, w1p.x, acc[2]);
            acc[3] = ffma2(xv, w1p.y, acc[3]);
            acc[4] = ffma2(xv, w2p.x, acc[4]);
            acc[5] = ffma2(xv, w2p.y, acc[5]);
            acc[6] = ffma2(xv, w3p.x, acc[6]);
            acc[7] = ffma2(xv, w3p.y, acc[7]);
        }
    }
    __syncthreads();

    float* red  = &xs[0][0];
    float* dred = &lgs[0][0];
    #pragma unroll
    for (int s = 0; s < SS; s++){
        float a, bq; up2(acc[s], a, bq);
        red[w*512 + s*64 + 2*lane]   = a;
        red[w*512 + s*64 + 2*lane+1] = bq;
    }
    if (tid < 64){
        #pragma unroll
        for (int s = 0; s < SS; s++) dred[s*64 + tid] = dsum[s];
    }
    __syncthreads();
    #pragma unroll
    for (int k = 0; k < 2; k++){
        int o = tid + k*256;
        float sum = 0.f;
        #pragma unroll
        for (int ww = 0; ww < 8; ww++) sum += red[ww*512 + o];
        g_prep[p*NROW*DD + b*512 + o] = sum;
    }
    if (tid < 8){
        float sum = 0.f;
        #pragma unroll
        for (int t2 = 0; t2 < 64; t2++) sum += dred[tid*64 + t2];
        g_denp[p*NROW + b*SS + tid] = sum;
    }
}

// ---------------- slot update: 256 threads/row, float4 weights -------------
__global__ void __launch_bounds__(256) k_update(int init, int wout,
    const float* __restrict__ eps, const float* __restrict__ mu,
    const float* __restrict__ lv,
    const float* __restrict__ bih, const float* __restrict__ bhh,
    const float* __restrict__ nrw, const float* __restrict__ nrb,
    const float* __restrict__ b2,  const float* __restrict__ nsw,
    const float* __restrict__ nsb,
    float* __restrict__ out_slots){
    int r = blockIdx.x;
    int tid = threadIdx.x, d = tid & 63, q = tid >> 6;
    int lane = tid & 31, w = tid >> 5;
    __shared__ __align__(16) float av[64], hp[64], tt[64], mm[128];
    __shared__ float pp[4][144];
    __shared__ float pg[6][4][64];
    __shared__ float ps[8], pq2[8];
    float h2;
    if (!init){
        float den = 0.f;
        #pragma unroll
        for (int p = 0; p < NPART; p++) den += g_denp[p*NROW + r];
        if (tid == 0 && wout) g_dent[r] = den;
        float pre = 0.f;
        #pragma unroll
        for (int p = 0; p < NPART; p++) pre += g_prep[p*NROW*DD + r*64 + d];
        if (q == 0){ av[d] = pre/den; hp[d] = g_slots[r*64 + d]; }
        __syncthreads();
        float at = 0.f;
        #pragma unroll
        for (int k = 0; k < 4; k++){
            int e4 = q*4 + k;
            float4 a4 = *(const float4*)&av[e4*4];
            float4 w4 = g_vw4[e4*64 + d];
            DOT4(at, a4, w4);
        }
        pp[q][d] = at;
        __syncthreads();
        at = (pp[0][d]+pp[1][d]) + (pp[2][d]+pp[3][d]);
        __syncthreads();
        if (q == 0) av[d] = at;
        __syncthreads();
        float gr=0.f, gz=0.f, gn=0.f, hr=0.f, hz=0.f, hn=0.f;
        #pragma unroll
        for (int k = 0; k < 4; k++){
            int e4 = q*4 + k;
            float4 a4 = *(const float4*)&av[e4*4];
            float4 h4 = *(const float4*)&hp[e4*4];
            const float4* wi = &g_wih4[e4*192];
            const float4* wh = &g_whh4[e4*192];
            float4 w4;
            w4 = wi[d];     DOT4(gr, a4, w4);
            w4 = wi[64+d];  DOT4(gz, a4, w4);
            w4 = wi[128+d]; DOT4(gn, a4, w4);
            w4 = wh[d];     DOT4(hr, h4, w4);
            w4 = wh[64+d];  DOT4(hz, h4, w4);
            w4 = wh[128+d]; DOT4(hn, h4, w4);
        }
        pg[0][q][d]=gr; pg[1][q][d]=gz; pg[2][q][d]=gn;
        pg[3][q][d]=hr; pg[4][q][d]=hz; pg[5][q][d]=hn;
        __syncthreads();
        gr = bih[d]; gz = bih[64+d]; gn = bih[128+d];
        hr = bhh[d]; hz = bhh[64+d]; hn = bhh[128+d];
        #pragma unroll
        for (int k = 0; k < 4; k++){
            gr += pg[0][k][d]; gz += pg[1][k][d]; gn += pg[2][k][d];
            hr += pg[3][k][d]; hz += pg[4][k][d]; hn += pg[5][k][d];
        }
        float rg = 1.f/(1.f + __expf(-(gr+hr)));
        float zg = 1.f/(1.f + __expf(-(gz+hz)));
        float ng = tanhf(gn + rg*hn);
        float h = (1.f-zg)*ng + zg*hp[d];
        float s = h, qs = h*h;
        #pragma unroll
        for (int o = 16; o; o >>= 1){
            s  += __shfl_xor_sync(~0u, s,  o);
            qs += __shfl_xor_sync(~0u, qs, o);
        }
        if (lane == 0){ ps[w] = s; pq2[w] = qs; }
        __syncthreads();
        int wb = w & ~1;
        s = ps[wb] + ps[wb+1]; qs = pq2[wb] + pq2[wb+1];
        float m = s*(1.f/64.f);
        float rs = rsqrtf(qs*(1.f/64.f) - m*m + 1e-5f);
        float ttv = (h-m)*rs*nrw[d] + nrb[d];
        __syncthreads();
        if (q == 0) tt[d] = ttv;
        __syncthreads();
        int j = tid & 127, hq = tid >> 7;
        float m1 = 0.f;
        #pragma unroll
        for (int k = 0; k < 8; k++){
            int e4 = hq*8 + k;
            float4 t4 = *(const float4*)&tt[e4*4];
            float4 w4 = g_w14[e4*128 + j];
            DOT4(m1, t4, w4);
        }
        pp[hq][j] = m1;
        __syncthreads();
        if (hq == 0) mm[j] = fmaxf(pp[0][j] + pp[1][j], 0.f);
        __syncthreads();
        float o2 = 0.f;
        #pragma unroll
        for (int k = 0; k < 8; k++){
            int j4 = q*8 + k;
            float4 m4 = *(const float4*)&mm[j4*4];
            float4 w4 = g_w24[j4*64 + d];
            DOT4(o2, m4, w4);
        }
        pp[q][d] = o2;
        __syncthreads();
        h2 = h + b2[d] + (pp[0][d]+pp[1][d]) + (pp[2][d]+pp[3][d]);
        __syncthreads();
    } else {
        h2 = mu[d] + __expf(0.5f*lv[d])*eps[r*64 + d];
    }
    if (q == 0){
        g_slots[r*64 + d] = h2;
        if (wout) out_slots[r*64 + d] = h2;
    }
    float s2 = h2, q2s = h2*h2;
    #pragma unroll
    for (int o = 16; o; o >>= 1){
        s2  += __shfl_xor_sync(~0u, s2,  o);
        q2s += __shfl_xor_sync(~0u, q2s, o);
    }
    if (lane == 0){ ps[w] = s2; pq2[w] = q2s; }
    __syncthreads();
    int wb2 = w & ~1;
    s2 = ps[wb2] + ps[wb2+1]; q2s = pq2[wb2] + pq2[wb2+1];
    float m2 = s2*(1.f/64.f);
    float rs2 = rsqrtf(q2s*(1.f/64.f) - m2*m2 + 1e-5f);
    float ttv2 = (h2-m2)*rs2*nsw[d] + nsb[d];
    __syncthreads();
    if (q == 0) tt[d] = ttv2;
    __syncthreads();
    float qd = 0.f;
    #pragma unroll
    for (int k = 0; k < 4; k++){
        int e4 = q*4 + k;
        float4 t4 = *(const float4*)&tt[e4*4];
        float4 w4 = g_qw4[e4*64 + d];
        DOT4(qd, t4, w4);
    }
    pp[q][d] = qd;
    __syncthreads();
    float qv = (pp[0][d]+pp[1][d]) + (pp[2][d]+pp[3][d]);
    __syncthreads();
    if (q == 0) av[d] = qv;
    __syncthreads();
    float qk = 0.f;
    #pragma unroll
    for (int k = 0; k < 4; k++){
        int e4 = q*4 + k;
        float4 a4 = *(const float4*)&av[e4*4];
        float4 w4 = g_kw4[e4*64 + d];
        DOT4(qk, a4, w4);
    }
    pp[q][d] = qk;
    __syncthreads();
    if (q == 0)
        g_qk[r*64 + d] = 0.125f*((pp[0][d]+pp[1][d]) + (pp[2][d]+pp[3][d]));
}

// ---------------- w = what / denom ----------------
__global__ void __launch_bounds__(256) k_wnorm(float* __restrict__ out_w){
    __shared__ float invd[8];
    int tok = blockIdx.x*256 + threadIdx.x;
    int b = tok >> 12;
    if (threadIdx.x < 8) invd[threadIdx.x] = 1.f/g_dent[b*SS + threadIdx.x];
    __syncthreads();
    float4* pw = (float4*)(out_w + (size_t)tok*SS);
    float4 a = pw[0], c = pw[1];
    a.x *= invd[0]; a.y *= invd[1]; a.z *= invd[2]; a.w *= invd[3];
    c.x *= invd[4]; c.y *= invd[5]; c.z *= invd[6]; c.w *= invd[7];
    pw[0] = a; pw[1] = c;
}

extern "C" void kernel_launch(void* const* d_in, const int* in_sizes, int n_in,
                              void* d_out, int out_size){
    const float* inp = (const float*)d_in[0];
    const float* eps = (const float*)d_in[1];
    const float* mu  = (const float*)d_in[2];
    const float* lv  = (const float*)d_in[3];
    const float* kw  = (const float*)d_in[4];
    const float* vw  = (const float*)d_in[5];
    const float* qw  = (const float*)d_in[6];
    const float* niw = (const float*)d_in[7];
    const float* nib = (const float*)d_in[8];
    const float* nsw = (const float*)d_in[9];
    const float* nsb = (const float*)d_in[10];
    const float* nrw = (const float*)d_in[11];
    const float* nrb = (const float*)d_in[12];
    const float* wih = (const float*)d_in[13];
    const float* whh = (const float*)d_in[14];
    const float* bih = (const float*)d_in[15];
    const float* bhh = (const float*)d_in[16];
    const float* w1  = (const float*)d_in[17];
    const float* w2  = (const float*)d_in[18];
    const float* b2  = (const float*)d_in[19];
    float* out_slots = (float*)d_out;
    float* out_w     = out_slots + NROW*DD;

    k_prep<<<2256, 256>>>(inp, niw, nib, vw, wih, whh, w1, w2, qw, kw);
    k_update<<<NROW, 256>>>(1, 0, eps, mu, lv, bih, bhh,
                            nrw, nrb, b2, nsw, nsb, out_slots);
    for (int step = 0; step < 4; step++){
        int fin = (step == 3);
        k_attn<<<dim3(NPART, BB), 256>>>(fin, out_w);
        k_update<<<NROW, 256>>>(0, fin, eps, mu, lv, bih, bhh,
                                nrw, nrb, b2, nsw, nsb, out_slots);
    }
    k_wnorm<<<NTOK/256, 256>>>(out_w);
}